// round 2
// baseline (speedup 1.0000x reference)
#include <cuda_runtime.h>
#include <cstdint>
#include <cstddef>

#define NNODES 10000
#define NEDGES 640000
#define HID    128
#define OUTD   10

// Scratch: PQ[n][0:128] = x[n] @ W1[0:128,:]   (P)
//          PQ[n][128:256] = x[n] @ W1[128:256,:] (Q)
__device__ float g_PQ[NNODES * 256];

// ---------- packed f32x2 helpers (Blackwell FFMA2 path) ----------
__device__ __forceinline__ unsigned long long f2_pack(float v) {
    unsigned long long d;
    unsigned int u = __float_as_uint(v);
    asm("mov.b64 %0, {%1, %2};" : "=l"(d) : "r"(u), "r"(u));
    return d;
}
__device__ __forceinline__ unsigned long long f2_fma(unsigned long long a,
                                                     unsigned long long b,
                                                     unsigned long long c) {
    unsigned long long d;
    asm("fma.rn.f32x2 %0, %1, %2, %3;" : "=l"(d) : "l"(a), "l"(b), "l"(c));
    return d;
}
__device__ __forceinline__ unsigned long long f2_add(unsigned long long a,
                                                     unsigned long long b) {
    unsigned long long d;
    asm("add.rn.f32x2 %0, %1, %2;" : "=l"(d) : "l"(a), "l"(b));
    return d;
}
__device__ __forceinline__ void f2_unpack(unsigned long long v, float& lo, float& hi) {
    unsigned int a, b;
    asm("mov.b64 {%0, %1}, %2;" : "=r"(a), "=r"(b) : "l"(v));
    lo = __uint_as_float(a);
    hi = __uint_as_float(b);
}

// ============================================================================
// Phase 1: PQ = x @ Bcat   (M=10000, N=256, K=128)
// Bcat[k][j] = W1[k][j] for j<128, else W1[k+128][j-128]
// Tiles: BM=64, BN=64, BK=64; 256 threads; 4x4 accumulators per thread.
// ============================================================================
__global__ void __launch_bounds__(256) phase1_kernel(const float* __restrict__ x,
                                                     const float* __restrict__ W1) {
    __shared__ float As[64][68];   // [m][k], padded
    __shared__ float Bs[64][68];   // [k][n], padded

    const int tid = threadIdx.x;
    const int m0 = blockIdx.x * 64;
    const int n0 = blockIdx.y * 64;
    const int tr = (tid >> 4) << 2;   // 0..60
    const int tc = (tid & 15) << 2;   // 0..60

    const int wRow = (n0 < 128) ? 0 : 128;
    const int wCol = (n0 < 128) ? n0 : (n0 - 128);

    float acc[4][4] = {};

    for (int k0 = 0; k0 < 128; k0 += 64) {
        // Load A tile: 64 rows x 64 k  (1024 float4, 4 per thread)
        #pragma unroll
        for (int i = 0; i < 4; i++) {
            int idx = tid + i * 256;
            int m = idx >> 4, kq = idx & 15;
            int gm = m0 + m;
            float4 v = make_float4(0.f, 0.f, 0.f, 0.f);
            if (gm < NNODES) v = *(const float4*)(x + (size_t)gm * HID + k0 + kq * 4);
            *(float4*)&As[m][kq * 4] = v;
        }
        // Load B tile from the proper half of W1
        #pragma unroll
        for (int i = 0; i < 4; i++) {
            int idx = tid + i * 256;
            int kk = idx >> 4, cq = idx & 15;
            float4 v = *(const float4*)(W1 + (size_t)(k0 + kk + wRow) * HID + wCol + cq * 4);
            *(float4*)&Bs[kk][cq * 4] = v;
        }
        __syncthreads();

        #pragma unroll
        for (int k = 0; k < 64; k++) {
            float4 b = *(const float4*)&Bs[k][tc];
            float a0 = As[tr + 0][k];
            float a1 = As[tr + 1][k];
            float a2 = As[tr + 2][k];
            float a3 = As[tr + 3][k];
            acc[0][0] += a0 * b.x; acc[0][1] += a0 * b.y; acc[0][2] += a0 * b.z; acc[0][3] += a0 * b.w;
            acc[1][0] += a1 * b.x; acc[1][1] += a1 * b.y; acc[1][2] += a1 * b.z; acc[1][3] += a1 * b.w;
            acc[2][0] += a2 * b.x; acc[2][1] += a2 * b.y; acc[2][2] += a2 * b.z; acc[2][3] += a2 * b.w;
            acc[3][0] += a3 * b.x; acc[3][1] += a3 * b.y; acc[3][2] += a3 * b.z; acc[3][3] += a3 * b.w;
        }
        __syncthreads();
    }

    #pragma unroll
    for (int r = 0; r < 4; r++) {
        int gm = m0 + tr + r;
        if (gm < NNODES) {
            *(float4*)(g_PQ + (size_t)gm * 256 + n0 + tc) =
                make_float4(acc[r][0], acc[r][1], acc[r][2], acc[r][3]);
        }
    }
}

// ============================================================================
// Phase 2: per edge e: h = relu(P[src] + Q[dst] + b1); out = h @ W2 + b2
// Block = 256 threads handles 64 edges. Gathered rows staged coalesced into
// smem (row stride 132 floats -> conflict-free LDS.128 across lanes).
// 4 threads per edge split the j-range; partials reduced via smem (f32x2).
// NOTE: edge_index arrives as int32 (JAX x64-disabled downcasts jnp.int64).
// ============================================================================
#define P2_SMEM_BYTES 86016

__global__ void __launch_bounds__(256) phase2_kernel(const int* __restrict__ ei,
                                                     const float* __restrict__ b1,
                                                     const float* __restrict__ W2,
                                                     const float* __restrict__ b2,
                                                     float* __restrict__ out) {
    extern __shared__ float sm[];
    float* Pr  = sm;                  // [64][132]  (8448 floats)
    float* Qr  = sm + 8448;           // [64][132]
    float* b1s = sm + 16896;          // [128]
    float* w2f = sm + 17024;          // 640 x float2 (1280 floats), 8B aligned
    unsigned long long* part = (unsigned long long*)(sm + 18304); // [4*64*5]
    float* stage = sm + 20864;        // [640]

    const int tid = threadIdx.x;
    const int e0 = blockIdx.x * 64;

    // Stage W2 as (o,o+1) pairs: w2f[j*5+o2] = {W2[j][2o2], W2[j][2o2+1]}
    for (int i = tid; i < HID * 5; i += 256) {
        int j = i / 5, o2 = i - j * 5;
        ((float2*)w2f)[i] = make_float2(W2[j * OUTD + o2 * 2], W2[j * OUTD + o2 * 2 + 1]);
    }
    if (tid < HID) b1s[tid] = b1[tid];

    // Gather P rows (src) coalesced: each warp loads one 512B row per step
    #pragma unroll
    for (int i = 0; i < 8; i++) {
        int idx = tid + i * 256;
        int r = idx >> 5, f4 = idx & 31;
        int s = ei[e0 + r];
        float4 v = *(const float4*)(g_PQ + (size_t)s * 256 + f4 * 4);
        *(float4*)&Pr[r * 132 + f4 * 4] = v;
    }
    // Gather Q rows (dst), second half of PQ row
    #pragma unroll
    for (int i = 0; i < 8; i++) {
        int idx = tid + i * 256;
        int r = idx >> 5, f4 = idx & 31;
        int d = ei[NEDGES + e0 + r];
        float4 v = *(const float4*)(g_PQ + (size_t)d * 256 + 128 + f4 * 4);
        *(float4*)&Qr[r * 132 + f4 * 4] = v;
    }
    __syncthreads();

    const int e = tid & 63;
    const int jseg = tid >> 6;               // 0..3, each covers 32 of 128 j's
    const float* Pe = Pr + e * 132 + jseg * 32;
    const float* Qe = Qr + e * 132 + jseg * 32;
    const float* be = b1s + jseg * 32;
    const unsigned long long* w2u = (const unsigned long long*)w2f;

    unsigned long long acc0 = 0ull, acc1 = 0ull, acc2 = 0ull, acc3 = 0ull, acc4 = 0ull;

    #pragma unroll
    for (int i = 0; i < 8; i++) {
        float4 p = *(const float4*)(Pe + i * 4);
        float4 q = *(const float4*)(Qe + i * 4);
        float4 b = *(const float4*)(be + i * 4);
        int j = jseg * 32 + i * 4;
        float v; unsigned long long vv; const unsigned long long* w;

        v = fmaxf(p.x + q.x + b.x, 0.f); vv = f2_pack(v); w = w2u + (size_t)(j + 0) * 5;
        acc0 = f2_fma(vv, w[0], acc0); acc1 = f2_fma(vv, w[1], acc1); acc2 = f2_fma(vv, w[2], acc2);
        acc3 = f2_fma(vv, w[3], acc3); acc4 = f2_fma(vv, w[4], acc4);

        v = fmaxf(p.y + q.y + b.y, 0.f); vv = f2_pack(v); w = w2u + (size_t)(j + 1) * 5;
        acc0 = f2_fma(vv, w[0], acc0); acc1 = f2_fma(vv, w[1], acc1); acc2 = f2_fma(vv, w[2], acc2);
        acc3 = f2_fma(vv, w[3], acc3); acc4 = f2_fma(vv, w[4], acc4);

        v = fmaxf(p.z + q.z + b.z, 0.f); vv = f2_pack(v); w = w2u + (size_t)(j + 2) * 5;
        acc0 = f2_fma(vv, w[0], acc0); acc1 = f2_fma(vv, w[1], acc1); acc2 = f2_fma(vv, w[2], acc2);
        acc3 = f2_fma(vv, w[3], acc3); acc4 = f2_fma(vv, w[4], acc4);

        v = fmaxf(p.w + q.w + b.w, 0.f); vv = f2_pack(v); w = w2u + (size_t)(j + 3) * 5;
        acc0 = f2_fma(vv, w[0], acc0); acc1 = f2_fma(vv, w[1], acc1); acc2 = f2_fma(vv, w[2], acc2);
        acc3 = f2_fma(vv, w[3], acc3); acc4 = f2_fma(vv, w[4], acc4);
    }

    unsigned long long* myp = part + ((size_t)jseg * 64 + e) * 5;
    myp[0] = acc0; myp[1] = acc1; myp[2] = acc2; myp[3] = acc3; myp[4] = acc4;
    __syncthreads();

    if (tid < 64) {
        float res[OUTD];
        #pragma unroll
        for (int o2 = 0; o2 < 5; o2++) {
            unsigned long long s = part[(size_t)tid * 5 + o2];
            s = f2_add(s, part[(size_t)(64 + tid) * 5 + o2]);
            s = f2_add(s, part[(size_t)(128 + tid) * 5 + o2]);
            s = f2_add(s, part[(size_t)(192 + tid) * 5 + o2]);
            f2_unpack(s, res[o2 * 2], res[o2 * 2 + 1]);
        }
        #pragma unroll
        for (int o = 0; o < OUTD; o++) stage[tid * OUTD + o] = res[o] + b2[o];
    }
    __syncthreads();

    // Coalesced store: 64 edges * 10 floats = 640 floats = 160 float4
    float4* ob = (float4*)(out + (size_t)blockIdx.x * 640);
    const float4* sg = (const float4*)stage;
    for (int i = tid; i < 160; i += 256) ob[i] = sg[i];
}

// ============================================================================
extern "C" void kernel_launch(void* const* d_in, const int* in_sizes, int n_in,
                              void* d_out, int out_size) {
    const float* x  = (const float*)d_in[0];
    const int*   ei = (const int*)d_in[1];
    const float* W1 = (const float*)d_in[2];
    const float* b1 = (const float*)d_in[3];
    const float* W2 = (const float*)d_in[4];
    const float* b2 = (const float*)d_in[5];
    float* out = (float*)d_out;

    cudaFuncSetAttribute(phase2_kernel,
                         cudaFuncAttributeMaxDynamicSharedMemorySize, P2_SMEM_BYTES);

    dim3 g1((NNODES + 63) / 64, 256 / 64);
    phase1_kernel<<<g1, 256>>>(x, W1);

    phase2_kernel<<<NEDGES / 64, 256, P2_SMEM_BYTES>>>(ei, b1, W2, b2, out);
}